// round 2
// baseline (speedup 1.0000x reference)
#include <cuda_runtime.h>
#include <cstdint>
#include <cstddef>

#define LN  1024
#define CC  16
#define NO  64

// ---------------- scratch (device globals; no allocation allowed) ----------
__device__ float d_diag[LN*CC];
__device__ float d_rows[LN*CC];   // row_sum[j,c] = sum_i Tm[i,j,c]
__device__ float d_cols[LN*CC];   // col_sum[i,c] = sum_j Tm[i,j,c]
__device__ float d_trace[CC];
__device__ float d_all[CC];
__device__ float d_A[LN*NO];      // A'[j] = blk1@diag[j]+blk9@row[j]+blk10@col[j] + consts + b1
__device__ float d_B[LN*NO];      // B[i]  = blk2@diag[i]+blk12@col[i]+blk13@row[i]
__device__ float d_D[LN*NO];      // D[k]  = blk0@diag+blk3@row+blk4@col+blk5@tr+blk11@all
__device__ int   g_mdt;           // mask dtype: 0=uint8(bool), 1=int32, 2=float32

// ---------------- mask dtype detector --------------------------------------
__global__ void k_detect(const unsigned char* __restrict__ M)
{
    int f32 = 0, u8 = 0;
    for (int w = 0; w < 1024; w++) {
        unsigned b0 = M[4*w+0], b1 = M[4*w+1], b2 = M[4*w+2], b3 = M[4*w+3];
        if (b0 > 1u || b1 > 1u || b2 > 1u || b3 > 1u) f32 = 1;
        if (b1 | b2 | b3) u8 = 1;
    }
    g_mdt = f32 ? 2 : (u8 ? 0 : 1);
}

__device__ __forceinline__ bool mask_at(const void* M, size_t idx, int mdt)
{
    if (mdt == 0) return ((const unsigned char*)M)[idx] != 0;
    if (mdt == 1) return ((const int*)M)[idx] != 0;
    return ((const float*)M)[idx] != 0.f;
}

// ---------------- pass 1: col sums (contiguous j) + diagonal ---------------
__global__ void k_colsum_diag(const float* __restrict__ T,
                              const void* __restrict__ M)
{
    const int mdt = g_mdt;
    const int i = blockIdx.x;
    const int t = threadIdx.x;          // 256
    const int c = t & 15, g = t >> 4;   // 16 groups over j
    float s = 0.f;
    for (int j = g; j < LN; j += 16) {
        size_t idx = ((size_t)i*LN + j)*CC + c;
        float v = T[idx];
        s += mask_at(M, idx, mdt) ? v : 0.f;
    }
    __shared__ float red[256];
    red[t] = s;
    __syncthreads();
    if (t < 16) {
        float tot = 0.f;
        #pragma unroll
        for (int g2 = 0; g2 < 16; g2++) tot += red[g2*16 + t];
        d_cols[i*CC + t] = tot;
        size_t di = ((size_t)i*LN + i)*CC + t;
        d_diag[i*CC + t] = mask_at(M, di, mdt) ? T[di] : 0.f;
    }
}

// ---------------- pass 2: row sums (strided i) -----------------------------
__global__ void k_rowsum(const float* __restrict__ T,
                         const void* __restrict__ M)
{
    const int mdt = g_mdt;
    const int j = blockIdx.x;
    const int t = threadIdx.x;
    const int c = t & 15, g = t >> 4;
    float s = 0.f;
    for (int i = g; i < LN; i += 16) {
        size_t idx = ((size_t)i*LN + j)*CC + c;
        float v = T[idx];
        s += mask_at(M, idx, mdt) ? v : 0.f;
    }
    __shared__ float red[256];
    red[t] = s;
    __syncthreads();
    if (t < 16) {
        float tot = 0.f;
        #pragma unroll
        for (int g2 = 0; g2 < 16; g2++) tot += red[g2*16 + t];
        d_rows[j*CC + t] = tot;
    }
}

// ---------------- pass 3: trace / all_sum ----------------------------------
__global__ void k_totals()
{
    const int t = threadIdx.x;          // 256
    const int c = t & 15, g = t >> 4;
    float s1 = 0.f, s2 = 0.f;
    for (int k = g; k < LN; k += 16) {
        s1 += d_diag[k*CC + c];
        s2 += d_cols[k*CC + c];
    }
    __shared__ float r1[256], r2[256];
    r1[t] = s1; r2[t] = s2;
    __syncthreads();
    if (t < 16) {
        float a = 0.f, b = 0.f;
        #pragma unroll
        for (int g2 = 0; g2 < 16; g2++) { a += r1[g2*16 + t]; b += r2[g2*16 + t]; }
        d_trace[t] = a;
        d_all[t]   = b;
    }
}

// ---------------- pass 4: A', B, D precompute ------------------------------
// W1 is [64, 240]; 15 basis blocks of 16 channels, order per reference _basis15.
__global__ void k_prep_ABD(const float* __restrict__ W1,
                           const float* __restrict__ b1)
{
    const int k = blockIdx.x;   // node
    const int o = threadIdx.x;  // 64 outputs
    __shared__ float sd[16], sr[16], sc[16], st[16], sa[16];
    if (o < 16) {
        sd[o] = d_diag[k*CC + o];
        sr[o] = d_rows[k*CC + o];
        sc[o] = d_cols[k*CC + o];
        st[o] = d_trace[o];
        sa[o] = d_all[o];
    }
    __syncthreads();
    const float* w = W1 + o*240;
    float A = b1[o], B = 0.f, D = 0.f;
    #pragma unroll
    for (int c = 0; c < 16; c++) {
        // A': j-dependent (blocks 1,9,10) + constants (8,14)
        A = fmaf(w[ 1*16 + c], sd[c], A);
        A = fmaf(w[ 9*16 + c], sr[c], A);
        A = fmaf(w[10*16 + c], sc[c], A);
        A = fmaf(w[ 8*16 + c], st[c], A);
        A = fmaf(w[14*16 + c], sa[c], A);
        // B: i-dependent (blocks 2,12,13)
        B = fmaf(w[ 2*16 + c], sd[c], B);
        B = fmaf(w[12*16 + c], sc[c], B);
        B = fmaf(w[13*16 + c], sr[c], B);
        // D: diagonal extras (blocks 0,3,4,5,11)
        D = fmaf(w[ 0*16 + c], sd[c], D);
        D = fmaf(w[ 3*16 + c], sr[c], D);
        D = fmaf(w[ 4*16 + c], sc[c], D);
        D = fmaf(w[ 5*16 + c], st[c], D);
        D = fmaf(w[11*16 + c], sa[c], D);
    }
    d_A[k*NO + o] = A;
    d_B[k*NO + o] = B;
    d_D[k*NO + o] = D;
}

// ---------------- masked 16-channel vector load (dtype-aware) --------------
__device__ __forceinline__ void load_masked(const float* __restrict__ T,
                                            const void* __restrict__ M,
                                            size_t base, int mdt, float v[16])
{
    const float4* tp = reinterpret_cast<const float4*>(T + base);
    float4 a = tp[0], b = tp[1], c = tp[2], d = tp[3];
    float raw[16] = {a.x,a.y,a.z,a.w, b.x,b.y,b.z,b.w,
                     c.x,c.y,c.z,c.w, d.x,d.y,d.z,d.w};
    if (mdt == 1) {
        // int32 mask: 16 ints = 64 bytes
        const uint4* mp = reinterpret_cast<const uint4*>((const int*)M + base);
        uint4 m0 = mp[0], m1 = mp[1], m2 = mp[2], m3 = mp[3];
        unsigned mw[16] = {m0.x,m0.y,m0.z,m0.w, m1.x,m1.y,m1.z,m1.w,
                           m2.x,m2.y,m2.z,m2.w, m3.x,m3.y,m3.z,m3.w};
        #pragma unroll
        for (int k = 0; k < 16; k++) v[k] = mw[k] ? raw[k] : 0.f;
    } else if (mdt == 0) {
        // uint8 bool mask: 16 bytes
        uint4 mv = *reinterpret_cast<const uint4*>((const unsigned char*)M + base);
        unsigned mw[4] = {mv.x, mv.y, mv.z, mv.w};
        #pragma unroll
        for (int k = 0; k < 16; k++)
            v[k] = ((mw[k>>2] >> ((k&3)*8)) & 0xFFu) ? raw[k] : 0.f;
    } else {
        // float32 mask
        const float4* mp = reinterpret_cast<const float4*>((const float*)M + base);
        float4 m0 = mp[0], m1 = mp[1], m2 = mp[2], m3 = mp[3];
        float mw[16] = {m0.x,m0.y,m0.z,m0.w, m1.x,m1.y,m1.z,m1.w,
                        m2.x,m2.y,m2.z,m2.w, m3.x,m3.y,m3.z,m3.w};
        #pragma unroll
        for (int k = 0; k < 16; k++) v[k] = (mw[k] != 0.f) ? raw[k] : 0.f;
    }
}

// ---------------- main fused kernel ----------------------------------------
// 16x16 (i,j) tile per block, 256 threads, one element per thread.
__global__ __launch_bounds__(256)
void k_main(const float* __restrict__ T,
            const void* __restrict__ M,
            const float* __restrict__ W1,
            const float* __restrict__ W2,
            const float* __restrict__ b2,
            float* __restrict__ out)
{
    __shared__ float W8s[64*16];    // block 7 (identity term)
    __shared__ float W7s[64*16];    // block 6 (transpose term)
    __shared__ float W2t[64*64];    // W2 transposed: W2t[o][o2]
    __shared__ float As[16*65];     // pad to stride 65: kill 16-way conflict
    __shared__ float Bs[16*65];
    __shared__ float Ds[16*65];
    __shared__ float b2s[64];

    const int mdt = g_mdt;
    const int t  = threadIdx.x;
    const int i0 = blockIdx.y * 16, j0 = blockIdx.x * 16;

    for (int idx = t; idx < 64*16; idx += 256) {
        int o = idx >> 4, c = idx & 15;
        W8s[idx] = W1[o*240 + 7*16 + c];
        W7s[idx] = W1[o*240 + 6*16 + c];
    }
    for (int idx = t; idx < 64*64; idx += 256) {
        int o = idx >> 6, o2 = idx & 63;
        W2t[idx] = W2[o2*64 + o];
    }
    for (int idx = t; idx < 16*64; idx += 256) {
        int r = idx >> 6, o = idx & 63;
        As[r*65 + o] = d_A[(j0 + r)*NO + o];
        Bs[r*65 + o] = d_B[(i0 + r)*NO + o];
    }
    const bool diagTile = (i0 == j0);
    if (diagTile) {
        for (int idx = t; idx < 16*64; idx += 256) {
            int r = idx >> 6, o = idx & 63;
            Ds[r*65 + o] = d_D[(i0 + r)*NO + o];
        }
    }
    if (t < 64) b2s[t] = b2[t];
    __syncthreads();

    const int il = t >> 4, jl = t & 15;
    const int i = i0 + il, j = j0 + jl;

    float tv[16], ttv[16];
    load_masked(T, M, ((size_t)i*LN + j)*CC, mdt, tv);   // Tm[i,j,:]
    load_masked(T, M, ((size_t)j*LN + i)*CC, mdt, ttv);  // Tm[j,i,:]

    // ---- phase 1: u = A'[j] + B[i] + W8@t + W7@tt (+ D on diagonal) ----
    float u[64];
    #pragma unroll
    for (int o = 0; o < 64; o++) {
        float a = As[jl*65 + o] + Bs[il*65 + o];
        const float* w8 = &W8s[o*16];
        const float* w7 = &W7s[o*16];
        #pragma unroll
        for (int c = 0; c < 16; c++) a = fmaf(w8[c], tv[c], a);
        #pragma unroll
        for (int c = 0; c < 16; c++) a = fmaf(w7[c], ttv[c], a);
        u[o] = a;
    }
    if (diagTile && i == j) {
        #pragma unroll
        for (int o = 0; o < 64; o++) u[o] += Ds[il*65 + o];
    }
    #pragma unroll
    for (int o = 0; o < 64; o++) u[o] = fmaxf(u[o], 0.f);

    // ---- phase 2: out = W2 @ relu(u) + b2, in 4 chunks of 16 outputs ----
    float* outp = out + ((size_t)i*LN + j)*NO;
    for (int ch = 0; ch < 4; ch++) {
        float acc[16];
        #pragma unroll
        for (int k = 0; k < 16; k++) acc[k] = b2s[ch*16 + k];
        #pragma unroll
        for (int o = 0; o < 64; o++) {
            float v = u[o];
            const float4* wp = reinterpret_cast<const float4*>(&W2t[o*64 + ch*16]);
            float w[16];
            *reinterpret_cast<float4*>(&w[0])  = wp[0];
            *reinterpret_cast<float4*>(&w[4])  = wp[1];
            *reinterpret_cast<float4*>(&w[8])  = wp[2];
            *reinterpret_cast<float4*>(&w[12]) = wp[3];
            #pragma unroll
            for (int k = 0; k < 16; k++) acc[k] = fmaf(w[k], v, acc[k]);
        }
        #pragma unroll
        for (int k = 0; k < 4; k++) {
            float4 s;
            s.x = acc[k*4+0]; s.y = acc[k*4+1]; s.z = acc[k*4+2]; s.w = acc[k*4+3];
            reinterpret_cast<float4*>(outp)[ch*4 + k] = s;
        }
    }
}

// ---------------- launch ----------------------------------------------------
extern "C" void kernel_launch(void* const* d_in, const int* in_sizes, int n_in,
                              void* d_out, int out_size)
{
    const float* T  = (const float*)d_in[0];
    const void*  M  = d_in[1];                    // dtype auto-detected
    const float* W1 = (const float*)d_in[2];
    const float* b1 = (const float*)d_in[3];
    const float* W2 = (const float*)d_in[4];
    const float* b2 = (const float*)d_in[5];
    float*       out = (float*)d_out;

    k_detect<<<1, 1>>>((const unsigned char*)M);
    k_colsum_diag<<<LN, 256>>>(T, M);
    k_rowsum<<<LN, 256>>>(T, M);
    k_totals<<<1, 256>>>();
    k_prep_ABD<<<LN, 64>>>(W1, b1);

    dim3 grid(LN/16, LN/16);
    k_main<<<grid, 256>>>(T, M, W1, W2, b2, out);
}

// round 5
// speedup vs baseline: 1.5121x; 1.5121x over previous
#include <cuda_runtime.h>
#include <cstdint>
#include <cstddef>

#define LN  1024
#define CC  16
#define NO  64
#define PAD 92          // buf row stride (floats): 92 mod 32 = 28 -> bank-unique frag loads
#define K1T 11          // GEMM1 k-tiles (K=88: 80 real + 1.0-col + pad)

// ===================== scratch globals ======================================
__device__ float d_diag[LN*CC];
__device__ float d_rows[LN*CC];
__device__ float d_cols[LN*CC];
__device__ float d_trace[CC];
__device__ float d_all[CC];
__device__ float d_CB[LN*NO];    // tf32-rounded: b1 + consts(trace,all) + B[i]
__device__ float d_D[LN*NO];     // fp32 diagonal extra
__device__ float d_Wf[NO*80];    // tf32-rounded [o][k]: blocks 7,6,1,9,10
__device__ float d_W2c[NO*NO];   // tf32-rounded copy of W2
__device__ int   g_mdt;          // 0=uint8 bool, 1=int32, 2=float32

// ===================== helpers ==============================================
__device__ __forceinline__ uint32_t tf32b(float x) {
    uint32_t u;
    asm("cvt.rna.tf32.f32 %0, %1;" : "=r"(u) : "f"(x));
    return u;
}
__device__ __forceinline__ float tf32f(float x) { return __uint_as_float(tf32b(x)); }

__device__ __forceinline__ void mma8(float c[4], const uint32_t a[4],
                                     uint32_t b0, uint32_t b1) {
    asm volatile(
        "mma.sync.aligned.m16n8k8.row.col.f32.tf32.tf32.f32 "
        "{%0,%1,%2,%3}, {%4,%5,%6,%7}, {%8,%9}, {%0,%1,%2,%3};"
        : "+f"(c[0]), "+f"(c[1]), "+f"(c[2]), "+f"(c[3])
        : "r"(a[0]), "r"(a[1]), "r"(a[2]), "r"(a[3]), "r"(b0), "r"(b1));
}

// ===================== mask handling ========================================
__global__ void k_detect(const unsigned char* __restrict__ M)
{
    int f32 = 0, u8 = 0;
    for (int w = 0; w < 1024; w++) {
        unsigned b0 = M[4*w+0], b1 = M[4*w+1], b2 = M[4*w+2], b3 = M[4*w+3];
        if (b0 > 1u || b1 > 1u || b2 > 1u || b3 > 1u) f32 = 1;
        if (b1 | b2 | b3) u8 = 1;
    }
    g_mdt = f32 ? 2 : (u8 ? 0 : 1);
}

__device__ __forceinline__ bool mask_at(const void* M, size_t idx, int mdt)
{
    if (mdt == 0) return ((const unsigned char*)M)[idx] != 0;
    if (mdt == 1) return ((const int*)M)[idx] != 0;
    return ((const float*)M)[idx] != 0.f;
}

__device__ __forceinline__ void load_masked(const float* __restrict__ T,
                                            const void* __restrict__ M,
                                            size_t base, int mdt, float v[16])
{
    const float4* tp = reinterpret_cast<const float4*>(T + base);
    float4 a = tp[0], b = tp[1], c = tp[2], d = tp[3];
    float raw[16] = {a.x,a.y,a.z,a.w, b.x,b.y,b.z,b.w,
                     c.x,c.y,c.z,c.w, d.x,d.y,d.z,d.w};
    if (mdt == 1) {
        const uint4* mp = reinterpret_cast<const uint4*>((const int*)M + base);
        uint4 m0 = mp[0], m1 = mp[1], m2 = mp[2], m3 = mp[3];
        unsigned mw[16] = {m0.x,m0.y,m0.z,m0.w, m1.x,m1.y,m1.z,m1.w,
                           m2.x,m2.y,m2.z,m2.w, m3.x,m3.y,m3.z,m3.w};
        #pragma unroll
        for (int k = 0; k < 16; k++) v[k] = mw[k] ? raw[k] : 0.f;
    } else if (mdt == 0) {
        uint4 mv = *reinterpret_cast<const uint4*>((const unsigned char*)M + base);
        unsigned mw[4] = {mv.x, mv.y, mv.z, mv.w};
        #pragma unroll
        for (int k = 0; k < 16; k++)
            v[k] = ((mw[k>>2] >> ((k&3)*8)) & 0xFFu) ? raw[k] : 0.f;
    } else {
        const float4* mp = reinterpret_cast<const float4*>((const float*)M + base);
        float4 m0 = mp[0], m1 = mp[1], m2 = mp[2], m3 = mp[3];
        float mw[16] = {m0.x,m0.y,m0.z,m0.w, m1.x,m1.y,m1.z,m1.w,
                        m2.x,m2.y,m2.z,m2.w, m3.x,m3.y,m3.z,m3.w};
        #pragma unroll
        for (int k = 0; k < 16; k++) v[k] = (mw[k] != 0.f) ? raw[k] : 0.f;
    }
}

// ===================== prep passes ==========================================
__global__ void k_colsum_diag(const float* __restrict__ T, const void* __restrict__ M)
{
    const int mdt = g_mdt;
    const int i = blockIdx.x, t = threadIdx.x;
    const int c = t & 15, g = t >> 4;
    float s = 0.f;
    for (int j = g; j < LN; j += 16) {
        size_t idx = ((size_t)i*LN + j)*CC + c;
        s += mask_at(M, idx, mdt) ? T[idx] : 0.f;
    }
    __shared__ float red[256];
    red[t] = s; __syncthreads();
    if (t < 16) {
        float tot = 0.f;
        #pragma unroll
        for (int g2 = 0; g2 < 16; g2++) tot += red[g2*16 + t];
        d_cols[i*CC + t] = tot;
        size_t di = ((size_t)i*LN + i)*CC + t;
        d_diag[i*CC + t] = mask_at(M, di, mdt) ? T[di] : 0.f;
    }
}

__global__ void k_rowsum(const float* __restrict__ T, const void* __restrict__ M)
{
    const int mdt = g_mdt;
    const int j = blockIdx.x, t = threadIdx.x;
    const int c = t & 15, g = t >> 4;
    float s = 0.f;
    for (int i = g; i < LN; i += 16) {
        size_t idx = ((size_t)i*LN + j)*CC + c;
        s += mask_at(M, idx, mdt) ? T[idx] : 0.f;
    }
    __shared__ float red[256];
    red[t] = s; __syncthreads();
    if (t < 16) {
        float tot = 0.f;
        #pragma unroll
        for (int g2 = 0; g2 < 16; g2++) tot += red[g2*16 + t];
        d_rows[j*CC + t] = tot;
    }
}

__global__ void k_totals()
{
    const int t = threadIdx.x;
    const int c = t & 15, g = t >> 4;
    float s1 = 0.f, s2 = 0.f;
    for (int k = g; k < LN; k += 16) {
        s1 += d_diag[k*CC + c];
        s2 += d_cols[k*CC + c];
    }
    __shared__ float r1[256], r2[256];
    r1[t] = s1; r2[t] = s2; __syncthreads();
    if (t < 16) {
        float a = 0.f, b = 0.f;
        #pragma unroll
        for (int g2 = 0; g2 < 16; g2++) { a += r1[g2*16 + t]; b += r2[g2*16 + t]; }
        d_trace[t] = a; d_all[t] = b;
    }
}

// CB[i][o] = b1 + blk8@trace + blk14@all + blk2@diag[i] + blk12@cols[i] + blk13@rows[i]
// D [i][o] = blk0@diag[i] + blk3@rows[i] + blk4@cols[i] + blk5@trace + blk11@all
__global__ void k_prep_CBD(const float* __restrict__ W1, const float* __restrict__ b1)
{
    const int k = blockIdx.x, o = threadIdx.x;
    __shared__ float sd[16], sr[16], sc[16], st[16], sa[16];
    if (o < 16) {
        sd[o] = d_diag[k*CC + o]; sr[o] = d_rows[k*CC + o];
        sc[o] = d_cols[k*CC + o]; st[o] = d_trace[o]; sa[o] = d_all[o];
    }
    __syncthreads();
    const float* w = W1 + o*240;
    float CB = b1[o], D = 0.f;
    #pragma unroll
    for (int c = 0; c < 16; c++) {
        CB = fmaf(w[ 8*16 + c], st[c], CB);
        CB = fmaf(w[14*16 + c], sa[c], CB);
        CB = fmaf(w[ 2*16 + c], sd[c], CB);
        CB = fmaf(w[12*16 + c], sc[c], CB);
        CB = fmaf(w[13*16 + c], sr[c], CB);
        D  = fmaf(w[ 0*16 + c], sd[c], D);
        D  = fmaf(w[ 3*16 + c], sr[c], D);
        D  = fmaf(w[ 4*16 + c], sc[c], D);
        D  = fmaf(w[ 5*16 + c], st[c], D);
        D  = fmaf(w[11*16 + c], sa[c], D);
    }
    d_CB[k*NO + o] = tf32f(CB);
    d_D[k*NO + o]  = D;
}

// d_Wf [o][0..79] = tf32(W1 blocks {7,6,1,9,10}); d_W2c = tf32(W2)
__global__ void k_prep_w(const float* __restrict__ W1, const float* __restrict__ W2)
{
    int idx = blockIdx.x * 256 + threadIdx.x;
    const int blksel[5] = {7, 6, 1, 9, 10};
    if (idx < NO*80) {
        int o = idx / 80, kk = idx % 80;
        d_Wf[idx] = tf32f(W1[o*240 + blksel[kk/16]*16 + (kk & 15)]);
    } else if (idx < NO*80 + NO*NO) {
        int q = idx - NO*80;
        d_W2c[q] = tf32f(W2[q]);
    }
}

// ===================== main mma.sync kernel =================================
// CTA: i = blockIdx.y, j-strip of 128 (blockIdx.x). 128 threads = 4 warps,
// each warp independently owns a 32-row M-strip.
__global__ __launch_bounds__(128)
void k_main_mma(const float* __restrict__ T,
                const void* __restrict__ M,
                const float* __restrict__ b2,
                float* __restrict__ out)
{
    __shared__ float buf[128 * PAD];

    const int mdt = g_mdt;
    const int tid = threadIdx.x;
    const int wid = tid >> 5, lane = tid & 31;
    const int t4 = lane >> 2, tq = lane & 3;   // groupID, threadID-in-group
    const int i  = blockIdx.y;
    const int j0 = blockIdx.x * 128;

    // ---- build X row r = tid (warp-private rows) -------------------------
    {
        const int r = tid;
        const int j = j0 + r;
        float tv[16], ttv[16];
        load_masked(T, M, ((size_t)i*LN + j)*CC, mdt, tv);
        load_masked(T, M, ((size_t)j*LN + i)*CC, mdt, ttv);
        float* row = buf + r * PAD;
        #pragma unroll
        for (int c = 0; c < 16; c++) row[c]      = tf32f(tv[c]);
        #pragma unroll
        for (int c = 0; c < 16; c++) row[16 + c] = tf32f(ttv[c]);
        const float4* dg = reinterpret_cast<const float4*>(d_diag + j*CC);
        const float4* rs = reinterpret_cast<const float4*>(d_rows + j*CC);
        const float4* cs = reinterpret_cast<const float4*>(d_cols + j*CC);
        #pragma unroll
        for (int q = 0; q < 4; q++) {
            float4 a = dg[q], b = rs[q], c = cs[q];
            row[32 + q*4 + 0] = tf32f(a.x); row[32 + q*4 + 1] = tf32f(a.y);
            row[32 + q*4 + 2] = tf32f(a.z); row[32 + q*4 + 3] = tf32f(a.w);
            row[48 + q*4 + 0] = tf32f(b.x); row[48 + q*4 + 1] = tf32f(b.y);
            row[48 + q*4 + 2] = tf32f(b.z); row[48 + q*4 + 3] = tf32f(b.w);
            row[64 + q*4 + 0] = tf32f(c.x); row[64 + q*4 + 1] = tf32f(c.y);
            row[64 + q*4 + 2] = tf32f(c.z); row[64 + q*4 + 3] = tf32f(c.w);
        }
        row[80] = 1.0f;
        #pragma unroll
        for (int c = 81; c < 88; c++) row[c] = 0.f;
    }
    __syncwarp();

    const float* bufw = buf + wid * 32 * PAD;

    // ---- GEMM1: u[32x64] = X[32x88] @ Wf_ext^T ---------------------------
    float u[2][8][4];
    #pragma unroll
    for (int m = 0; m < 2; m++)
        #pragma unroll
        for (int n = 0; n < 8; n++)
            #pragma unroll
            for (int c = 0; c < 4; c++) u[m][n][c] = 0.f;

    #pragma unroll
    for (int k = 0; k < 10; k++) {
        uint32_t a[2][4];
        #pragma unroll
        for (int m = 0; m < 2; m++) {
            const float* pr = bufw + (m*16 + t4)*PAD + k*8 + tq;
            a[m][0] = __float_as_uint(pr[0]);
            a[m][1] = __float_as_uint(pr[8*PAD]);
            a[m][2] = __float_as_uint(pr[4]);
            a[m][3] = __float_as_uint(pr[8*PAD + 4]);
        }
        #pragma unroll
        for (int n = 0; n < 8; n++) {
            uint32_t b0 = __float_as_uint(d_Wf[(n*8 + t4)*80 + k*8 + tq]);
            uint32_t b1 = __float_as_uint(d_Wf[(n*8 + t4)*80 + k*8 + 4 + tq]);
            mma8(u[0][n], a[0], b0, b1);
            mma8(u[1][n], a[1], b0, b1);
        }
    }
    {   // tail k-tile: col 80 = 1.0, weight = d_CB[i]
        uint32_t a[2][4];
        #pragma unroll
        for (int m = 0; m < 2; m++) {
            const float* pr = bufw + (m*16 + t4)*PAD + 80 + tq;
            a[m][0] = __float_as_uint(pr[0]);
            a[m][1] = __float_as_uint(pr[8*PAD]);
            a[m][2] = __float_as_uint(pr[4]);
            a[m][3] = __float_as_uint(pr[8*PAD + 4]);
        }
        #pragma unroll
        for (int n = 0; n < 8; n++) {
            uint32_t b0 = (tq == 0) ? __float_as_uint(d_CB[i*NO + n*8 + t4]) : 0u;
            mma8(u[0][n], a[0], b0, 0u);
            mma8(u[1][n], a[1], b0, 0u);
        }
    }

    // ---- epilogue 1: +D on diagonal, relu, tf32-round, store to buf ------
    #pragma unroll
    for (int m = 0; m < 2; m++) {
        const int r1 = wid*32 + m*16 + t4;
        const int r2 = r1 + 8;
        const bool dd1 = (j0 + r1 == i), dd2 = (j0 + r2 == i);
        #pragma unroll
        for (int n = 0; n < 8; n++) {
            const int col = n*8 + 2*tq;
            float v0 = u[m][n][0], v1 = u[m][n][1];
            float v2 = u[m][n][2], v3 = u[m][n][3];
            if (dd1) { v0 += d_D[i*NO + col]; v1 += d_D[i*NO + col + 1]; }
            if (dd2) { v2 += d_D[i*NO + col]; v3 += d_D[i*NO + col + 1]; }
            float2 s1, s2;
            s1.x = tf32f(fmaxf(v0, 0.f)); s1.y = tf32f(fmaxf(v1, 0.f));
            s2.x = tf32f(fmaxf(v2, 0.f)); s2.y = tf32f(fmaxf(v3, 0.f));
            *reinterpret_cast<float2*>(buf + r1*PAD + col) = s1;
            *reinterpret_cast<float2*>(buf + r2*PAD + col) = s2;
        }
    }
    __syncwarp();

    // ---- GEMM2: out[32x64] = relu(u)[32x64] @ W2^T -----------------------
    float o2[2][8][4];
    #pragma unroll
    for (int m = 0; m < 2; m++)
        #pragma unroll
        for (int n = 0; n < 8; n++)
            #pragma unroll
            for (int c = 0; c < 4; c++) o2[m][n][c] = 0.f;

    #pragma unroll
    for (int k = 0; k < 8; k++) {
        uint32_t a[2][4];
        #pragma unroll
        for (int m = 0; m < 2; m++) {
            const float* pr = bufw + (m*16 + t4)*PAD + k*8 + tq;
            a[m][0] = __float_as_uint(pr[0]);
            a[m][1] = __float_as_uint(pr[8*PAD]);
            a[m][2] = __float_as_uint(pr[4]);
            a[m][3] = __float_as_uint(pr[8*PAD + 4]);
        }
        #pragma unroll
        for (int n = 0; n < 8; n++) {
            uint32_t b0 = __float_as_uint(d_W2c[(n*8 + t4)*NO + k*8 + tq]);
            uint32_t b1 = __float_as_uint(d_W2c[(n*8 + t4)*NO + k*8 + 4 + tq]);
            mma8(o2[0][n], a[0], b0, b1);
            mma8(o2[1][n], a[1], b0, b1);
        }
    }

    // ---- epilogue 2: +b2, store (32B-sector aligned float2) --------------
    float2 b2v[8];
    #pragma unroll
    for (int n = 0; n < 8; n++)
        b2v[n] = *reinterpret_cast<const float2*>(b2 + n*8 + 2*tq);

    #pragma unroll
    for (int m = 0; m < 2; m++) {
        const int r1 = wid*32 + m*16 + t4;
        const int j1 = j0 + r1, j2 = j1 + 8;
        float* o1 = out + ((size_t)i*LN + j1)*NO;
        float* o8 = out + ((size_t)i*LN + j2)*NO;
        #pragma unroll
        for (int n = 0; n < 8; n++) {
            const int col = n*8 + 2*tq;
            float2 s1, s2;
            s1.x = o2[m][n][0] + b2v[n].x; s1.y = o2[m][n][1] + b2v[n].y;
            s2.x = o2[m][n][2] + b2v[n].x; s2.y = o2[m][n][3] + b2v[n].y;
            *reinterpret_cast<float2*>(o1 + col) = s1;
            *reinterpret_cast<float2*>(o8 + col) = s2;
        }
    }
}

// ===================== launch ===============================================
extern "C" void kernel_launch(void* const* d_in, const int* in_sizes, int n_in,
                              void* d_out, int out_size)
{
    const float* T  = (const float*)d_in[0];
    const void*  M  = d_in[1];
    const float* W1 = (const float*)d_in[2];
    const float* b1 = (const float*)d_in[3];
    const float* W2 = (const float*)d_in[4];
    const float* b2 = (const float*)d_in[5];
    float*       out = (float*)d_out;

    k_detect<<<1, 1>>>((const unsigned char*)M);
    k_colsum_diag<<<LN, 256>>>(T, M);
    k_rowsum<<<LN, 256>>>(T, M);
    k_totals<<<1, 256>>>();
    k_prep_CBD<<<LN, 64>>>(W1, b1);
    k_prep_w<<<(NO*80 + NO*NO + 255)/256, 256>>>(W1, W2);

    dim3 grid(LN/128, LN);
    k_main_mma<<<grid, 128>>>(T, M, b2, out);
}

// round 6
// speedup vs baseline: 2.0671x; 1.3670x over previous
#include <cuda_runtime.h>
#include <cstdint>
#include <cstddef>

#define LN  1024
#define CC  16
#define NO  64
#define PAD 76      // buf row stride: 76 mod 32 = 12 -> conflict-free frag LDS

// ===================== scratch globals ======================================
__device__ float d_Tm[LN*LN*CC];   // masked T, tf32-rounded
__device__ float d_Tt[LN*LN*CC];   // d_Tt[(i*LN+j)*CC+c] = Tm[j][i][c]
__device__ float d_diag[LN*CC];    // fp32
__device__ float d_rows[LN*CC];
__device__ float d_cols[LN*CC];
__device__ float d_trace[CC];
__device__ float d_all[CC];
__device__ float d_Afull[LN*NO];   // fp32: blk1@diag[j]+blk9@rows[j]+blk10@cols[j]
__device__ float d_CB[LN*NO];      // fp32: b1+blk8@tr+blk14@all+blk2@diag+blk12@cols+blk13@rows
__device__ float d_D[LN*NO];       // fp32 diagonal extra
__device__ float d_W1F[4*32*16];   // GEMM1 B frags, tf32: [(k*32+lane)*16 + 2n + h]
__device__ float d_W2F[8*32*16];   // GEMM2 B frags, tf32
__device__ int   g_mdt;            // 0=uint8 bool, 1=int32, 2=float32

// ===================== helpers ==============================================
__device__ __forceinline__ float tf32f(float x) {
    uint32_t u;
    asm("cvt.rna.tf32.f32 %0, %1;" : "=r"(u) : "f"(x));
    return __uint_as_float(u);
}
__device__ __forceinline__ void mma8(float c[4], const uint32_t a[4],
                                     uint32_t b0, uint32_t b1) {
    asm volatile(
        "mma.sync.aligned.m16n8k8.row.col.f32.tf32.tf32.f32 "
        "{%0,%1,%2,%3}, {%4,%5,%6,%7}, {%8,%9}, {%0,%1,%2,%3};"
        : "+f"(c[0]), "+f"(c[1]), "+f"(c[2]), "+f"(c[3])
        : "r"(a[0]), "r"(a[1]), "r"(a[2]), "r"(a[3]), "r"(b0), "r"(b1));
}
__device__ __forceinline__ bool mask_at(const void* M, size_t idx, int mdt)
{
    if (mdt == 0) return ((const unsigned char*)M)[idx] != 0;
    if (mdt == 1) return ((const int*)M)[idx] != 0;
    return ((const float*)M)[idx] != 0.f;
}

// ===================== launch 0: detect mask dtype + zero accumulators ======
__global__ void k_detect(const unsigned char* __restrict__ M)
{
    int f32 = 0, u8 = 0;
    for (int w = 0; w < 1024; w++) {
        unsigned b0 = M[4*w+0], b1 = M[4*w+1], b2 = M[4*w+2], b3 = M[4*w+3];
        if (b0 > 1u || b1 > 1u || b2 > 1u || b3 > 1u) f32 = 1;
        if (b1 | b2 | b3) u8 = 1;
    }
    g_mdt = f32 ? 2 : (u8 ? 0 : 1);
    for (int c = 0; c < CC; c++) { d_trace[c] = 0.f; d_all[c] = 0.f; }
}

// ===================== launch 1: mask+round -> Tm, colsum, diag, all/trace ==
__global__ void k_pass1(const float* __restrict__ T, const void* __restrict__ M)
{
    const int mdt = g_mdt;
    const int i = blockIdx.x, t = threadIdx.x;
    const int c = t & 15, g = t >> 4;
    float s = 0.f;
    for (int j = g; j < LN; j += 16) {
        size_t idx = ((size_t)i*LN + j)*CC + c;
        float v = mask_at(M, idx, mdt) ? T[idx] : 0.f;
        d_Tm[idx] = tf32f(v);
        s += v;
    }
    __shared__ float red[256];
    red[t] = s; __syncthreads();
    if (t < 16) {
        float tot = 0.f;
        #pragma unroll
        for (int g2 = 0; g2 < 16; g2++) tot += red[g2*16 + t];
        d_cols[i*CC + t] = tot;
        atomicAdd(&d_all[t], tot);
        size_t di = ((size_t)i*LN + i)*CC + t;
        float dv = mask_at(M, di, mdt) ? T[di] : 0.f;
        d_diag[i*CC + t] = dv;
        atomicAdd(&d_trace[t], dv);
    }
}

// ===================== launch 2: transpose Tm -> Tt, rowsum =================
__global__ void k_pass2()
{
    const int q = blockIdx.x, t = threadIdx.x;
    const int c = t & 15, g = t >> 4;
    float s = 0.f;
    for (int l = g; l < LN; l += 16) {
        size_t src = ((size_t)l*LN + q)*CC + c;
        float v = d_Tm[src];
        d_Tt[((size_t)q*LN + l)*CC + c] = v;
        s += v;
    }
    __shared__ float red[256];
    red[t] = s; __syncthreads();
    if (t < 16) {
        float tot = 0.f;
        #pragma unroll
        for (int g2 = 0; g2 < 16; g2++) tot += red[g2*16 + t];
        d_rows[q*CC + t] = tot;
    }
}

// ===================== launch 3: Afull / CB / D (all fp32) ==================
__global__ void k_prep_ACD(const float* __restrict__ W1, const float* __restrict__ b1)
{
    const int k = blockIdx.x, o = threadIdx.x;
    __shared__ float sd[16], sr[16], sc[16], st[16], sa[16];
    if (o < 16) {
        sd[o] = d_diag[k*CC + o]; sr[o] = d_rows[k*CC + o];
        sc[o] = d_cols[k*CC + o]; st[o] = d_trace[o]; sa[o] = d_all[o];
    }
    __syncthreads();
    const float* w = W1 + o*240;
    float A = 0.f, CB = b1[o], D = 0.f;
    #pragma unroll
    for (int c = 0; c < 16; c++) {
        A  = fmaf(w[ 1*16 + c], sd[c], A);
        A  = fmaf(w[ 9*16 + c], sr[c], A);
        A  = fmaf(w[10*16 + c], sc[c], A);
        CB = fmaf(w[ 8*16 + c], st[c], CB);
        CB = fmaf(w[14*16 + c], sa[c], CB);
        CB = fmaf(w[ 2*16 + c], sd[c], CB);
        CB = fmaf(w[12*16 + c], sc[c], CB);
        CB = fmaf(w[13*16 + c], sr[c], CB);
        D  = fmaf(w[ 0*16 + c], sd[c], D);
        D  = fmaf(w[ 3*16 + c], sr[c], D);
        D  = fmaf(w[ 4*16 + c], sc[c], D);
        D  = fmaf(w[ 5*16 + c], st[c], D);
        D  = fmaf(w[11*16 + c], sa[c], D);
    }
    d_Afull[k*NO + o] = A;
    d_CB[k*NO + o]    = CB;
    d_D[k*NO + o]     = D;
}

// ===================== launch 4: weight fragment layouts ====================
// b0(k,lane,n) = Wcol[(n*8+t4)][k*8+tq], b1 = ..[k*8+tq+4]
// flat index: (k*32+lane)*16 + 2n + h
__global__ void k_prep_w(const float* __restrict__ W1, const float* __restrict__ W2)
{
    int idx = blockIdx.x * 256 + threadIdx.x;
    if (idx < 4*32*16) {
        int s = idx & 15, lane = (idx >> 4) & 31, k = idx >> 9;
        int n = s >> 1, h = s & 1, t4 = lane >> 2, tq = lane & 3;
        int col = k*8 + tq + 4*h;                 // 0..31
        int o = n*8 + t4;
        float v = (col < 16) ? W1[o*240 + 7*16 + col]
                             : W1[o*240 + 6*16 + (col - 16)];
        d_W1F[idx] = tf32f(v);
    } else if (idx < 4*32*16 + 8*32*16) {
        int q = idx - 4*32*16;
        int s = q & 15, lane = (q >> 4) & 31, k = q >> 9;
        int n = s >> 1, h = s & 1, t4 = lane >> 2, tq = lane & 3;
        int col = k*8 + tq + 4*h;                 // 0..63
        d_W2F[q] = tf32f(W2[(n*8 + t4)*64 + col]);
    }
}

// ===================== launch 5: main mma kernel ============================
// CTA: i = blockIdx.y, 128-wide j strip = blockIdx.x. 4 warps, each owns 32 rows.
__global__ __launch_bounds__(128)
void k_main_mma(const float* __restrict__ b2, float* __restrict__ out)
{
    __shared__ float buf[128 * PAD];

    const int tid = threadIdx.x;
    const int wid = tid >> 5, lane = tid & 31;
    const int t4 = lane >> 2, tq = lane & 3;
    const int i  = blockIdx.y;
    const int j0 = blockIdx.x * 128;

    // ---- X build: cols 0..15 = Tm(i,j,:), 16..31 = Tm(j,i,:) -------------
    const float4* TmV = reinterpret_cast<const float4*>(d_Tm) + ((size_t)i*LN + j0)*4;
    const float4* TtV = reinterpret_cast<const float4*>(d_Tt) + ((size_t)i*LN + j0)*4;
    #pragma unroll
    for (int s = 0; s < 4; s++) {
        int idx = s*128 + tid;            // 0..511
        int r = idx >> 2, q = idx & 3;    // 4 consecutive lanes -> contiguous 64B
        *reinterpret_cast<float4*>(&buf[r*PAD + q*4])      = TmV[r*4 + q];
        *reinterpret_cast<float4*>(&buf[r*PAD + 16 + q*4]) = TtV[r*4 + q];
    }
    __syncthreads();

    const float* bufw = buf + wid * 32 * PAD;

    // ---- GEMM1: u[32x64] = X[32x32] @ Wf^T (4 k-tiles) -------------------
    float u[2][8][4];
    #pragma unroll
    for (int m = 0; m < 2; m++)
        #pragma unroll
        for (int n = 0; n < 8; n++)
            #pragma unroll
            for (int c = 0; c < 4; c++) u[m][n][c] = 0.f;

    #pragma unroll
    for (int k = 0; k < 4; k++) {
        uint32_t a[2][4];
        #pragma unroll
        for (int m = 0; m < 2; m++) {
            const float* pr = bufw + (m*16 + t4)*PAD + k*8 + tq;
            a[m][0] = __float_as_uint(pr[0]);
            a[m][1] = __float_as_uint(pr[8*PAD]);
            a[m][2] = __float_as_uint(pr[4]);
            a[m][3] = __float_as_uint(pr[8*PAD + 4]);
        }
        float4 bq[4];
        const float4* wp = reinterpret_cast<const float4*>(d_W1F + (k*32 + lane)*16);
        bq[0] = wp[0]; bq[1] = wp[1]; bq[2] = wp[2]; bq[3] = wp[3];
        const uint32_t* bb = reinterpret_cast<const uint32_t*>(bq);
        #pragma unroll
        for (int n = 0; n < 8; n++) {
            mma8(u[0][n], a[0], bb[2*n], bb[2*n+1]);
            mma8(u[1][n], a[1], bb[2*n], bb[2*n+1]);
        }
    }

    // ---- epilogue 1: + A[j] + CB[i] (+D diag), relu, tf32, store ---------
    float2 cb[8];
    #pragma unroll
    for (int n = 0; n < 8; n++)
        cb[n] = *reinterpret_cast<const float2*>(d_CB + i*NO + n*8 + 2*tq);

    #pragma unroll
    for (int m = 0; m < 2; m++) {
        const int r1 = wid*32 + m*16 + t4, r2 = r1 + 8;
        const int j1 = j0 + r1, j2 = j0 + r2;
        #pragma unroll
        for (int n = 0; n < 8; n++) {
            const int col = n*8 + 2*tq;
            float2 A1 = *reinterpret_cast<const float2*>(d_Afull + (size_t)j1*NO + col);
            float2 A2 = *reinterpret_cast<const float2*>(d_Afull + (size_t)j2*NO + col);
            float v0 = u[m][n][0] + A1.x + cb[n].x;
            float v1 = u[m][n][1] + A1.y + cb[n].y;
            float v2 = u[m][n][2] + A2.x + cb[n].x;
            float v3 = u[m][n][3] + A2.y + cb[n].y;
            if (j1 == i) {
                float2 dd = *reinterpret_cast<const float2*>(d_D + i*NO + col);
                v0 += dd.x; v1 += dd.y;
            }
            if (j2 == i) {
                float2 dd = *reinterpret_cast<const float2*>(d_D + i*NO + col);
                v2 += dd.x; v3 += dd.y;
            }
            float2 s1, s2;
            s1.x = tf32f(fmaxf(v0, 0.f)); s1.y = tf32f(fmaxf(v1, 0.f));
            s2.x = tf32f(fmaxf(v2, 0.f)); s2.y = tf32f(fmaxf(v3, 0.f));
            *reinterpret_cast<float2*>(&buf[r1*PAD + col]) = s1;
            *reinterpret_cast<float2*>(&buf[r2*PAD + col]) = s2;
        }
    }
    __syncwarp();

    // ---- GEMM2: out[32x64] = relu(u)[32x64] @ W2^T (8 k-tiles) -----------
    float o2[2][8][4];
    #pragma unroll
    for (int m = 0; m < 2; m++)
        #pragma unroll
        for (int n = 0; n < 8; n++)
            #pragma unroll
            for (int c = 0; c < 4; c++) o2[m][n][c] = 0.f;

    #pragma unroll
    for (int k = 0; k < 8; k++) {
        uint32_t a[2][4];
        #pragma unroll
        for (int m = 0; m < 2; m++) {
            const float* pr = bufw + (m*16 + t4)*PAD + k*8 + tq;
            a[m][0] = __float_as_uint(pr[0]);
            a[m][1] = __float_as_uint(pr[8*PAD]);
            a[m][2] = __float_as_uint(pr[4]);
            a[m][3] = __float_as_uint(pr[8*PAD + 4]);
        }
        float4 bq[4];
        const float4* wp = reinterpret_cast<const float4*>(d_W2F + (k*32 + lane)*16);
        bq[0] = wp[0]; bq[1] = wp[1]; bq[2] = wp[2]; bq[3] = wp[3];
        const uint32_t* bb = reinterpret_cast<const uint32_t*>(bq);
        #pragma unroll
        for (int n = 0; n < 8; n++) {
            mma8(o2[0][n], a[0], bb[2*n], bb[2*n+1]);
            mma8(o2[1][n], a[1], bb[2*n], bb[2*n+1]);
        }
    }

    // ---- epilogue 2: + b2, store -----------------------------------------
    float2 b2v[8];
    #pragma unroll
    for (int n = 0; n < 8; n++)
        b2v[n] = *reinterpret_cast<const float2*>(b2 + n*8 + 2*tq);

    #pragma unroll
    for (int m = 0; m < 2; m++) {
        const int r1 = wid*32 + m*16 + t4;
        const int j1 = j0 + r1, j2 = j1 + 8;
        float* o1 = out + ((size_t)i*LN + j1)*NO;
        float* o8 = out + ((size_t)i*LN + j2)*NO;
        #pragma unroll
        for (int n = 0; n < 8; n++) {
            const int col = n*8 + 2*tq;
            float2 s1, s2;
            s1.x = o2[m][n][0] + b2v[n].x; s1.y = o2[m][n][1] + b2v[n].y;
            s2.x = o2[m][n][2] + b2v[n].x; s2.y = o2[m][n][3] + b2v[n].y;
            *reinterpret_cast<float2*>(o1 + col) = s1;
            *reinterpret_cast<float2*>(o8 + col) = s2;
        }
    }
}

// ===================== launch ===============================================
extern "C" void kernel_launch(void* const* d_in, const int* in_sizes, int n_in,
                              void* d_out, int out_size)
{
    const float* T  = (const float*)d_in[0];
    const void*  M  = d_in[1];
    const float* W1 = (const float*)d_in[2];
    const float* b1 = (const float*)d_in[3];
    const float* W2 = (const float*)d_in[4];
    const float* b2 = (const float*)d_in[5];
    float*       out = (float*)d_out;

    k_detect<<<1, 1>>>((const unsigned char*)M);           // launch 0
    k_pass1<<<LN, 256>>>(T, M);                            // launch 1
    k_pass2<<<LN, 256>>>();                                // launch 2
    k_prep_ACD<<<LN, 64>>>(W1, b1);                        // launch 3
    k_prep_w<<<24, 256>>>(W1, W2);                         // launch 4

    dim3 grid(LN/128, LN);
    k_main_mma<<<grid, 128>>>(b2, out);                    // launch 5 (ncu -s5)
}

// round 7
// speedup vs baseline: 2.6291x; 1.2719x over previous
#include <cuda_runtime.h>
#include <cstdint>
#include <cstddef>

#define LN  1024
#define CC  16
#define NO  64
#define PAD 76      // buf row stride: 76 mod 32 = 12 -> conflict-free frag LDS/STS

// ===================== scratch globals ======================================
__device__ float d_Tm[LN*LN*CC];   // masked T, tf32-rounded (L2-resident, 64MB)
__device__ float d_diag[LN*CC];    // fp32
__device__ float d_rows[LN*CC];
__device__ float d_cols[LN*CC];
__device__ float d_trace[CC];
__device__ float d_all[CC];
__device__ float d_Afull[LN*NO];   // fp32: blk1@diag[j]+blk9@rows[j]+blk10@cols[j]
__device__ float d_CB[LN*NO];      // fp32: b1+blk8@tr+blk14@all+blk2@diag+blk12@cols+blk13@rows
__device__ float d_D[LN*NO];       // fp32 diagonal extra
__device__ float d_W1F[4*32*16];   // GEMM1 B frags, tf32: [(k*32+lane)*16 + 2n + h]
__device__ float d_W2F[8*32*16];   // GEMM2 B frags, tf32
__device__ int   g_mdt;            // 0=uint8 bool, 1=int32, 2=float32

// ===================== helpers ==============================================
__device__ __forceinline__ float tf32f(float x) {
    uint32_t u;
    asm("cvt.rna.tf32.f32 %0, %1;" : "=r"(u) : "f"(x));
    return __uint_as_float(u);
}
__device__ __forceinline__ void mma8(float c[4], const uint32_t a[4],
                                     uint32_t b0, uint32_t b1) {
    asm volatile(
        "mma.sync.aligned.m16n8k8.row.col.f32.tf32.tf32.f32 "
        "{%0,%1,%2,%3}, {%4,%5,%6,%7}, {%8,%9}, {%0,%1,%2,%3};"
        : "+f"(c[0]), "+f"(c[1]), "+f"(c[2]), "+f"(c[3])
        : "r"(a[0]), "r"(a[1]), "r"(a[2]), "r"(a[3]), "r"(b0), "r"(b1));
}
__device__ __forceinline__ bool mask_at(const void* M, size_t idx, int mdt)
{
    if (mdt == 0) return ((const unsigned char*)M)[idx] != 0;
    if (mdt == 1) return ((const int*)M)[idx] != 0;
    return ((const float*)M)[idx] != 0.f;
}

// ===================== launch 0: detect mask dtype (parallel) ==============
__global__ void k_detect(const unsigned char* __restrict__ M)
{
    __shared__ int sf32, su8;
    const int t = threadIdx.x;          // 256
    if (t == 0) { sf32 = 0; su8 = 0; }
    __syncthreads();
    int f32 = 0, u8 = 0;
    for (int w = t; w < 1024; w += 256) {
        unsigned b0 = M[4*w+0], b1 = M[4*w+1], b2 = M[4*w+2], b3 = M[4*w+3];
        if (b0 > 1u || b1 > 1u || b2 > 1u || b3 > 1u) f32 = 1;
        if (b1 | b2 | b3) u8 = 1;
    }
    if (f32) atomicOr(&sf32, 1);
    if (u8)  atomicOr(&su8, 1);
    __syncthreads();
    if (t == 0) g_mdt = sf32 ? 2 : (su8 ? 0 : 1);
    if (t < CC) { d_trace[t] = 0.f; d_all[t] = 0.f; }
}

// ===================== launch 1: mask+round -> Tm, colsum, diag, all/trace ==
__global__ void k_pass1(const float* __restrict__ T, const void* __restrict__ M)
{
    const int mdt = g_mdt;
    const int i = blockIdx.x, t = threadIdx.x;
    const int c = t & 15, g = t >> 4;
    float s = 0.f;
    for (int j = g; j < LN; j += 16) {
        size_t idx = ((size_t)i*LN + j)*CC + c;
        float v = mask_at(M, idx, mdt) ? T[idx] : 0.f;
        d_Tm[idx] = tf32f(v);
        s += v;
    }
    __shared__ float red[256];
    red[t] = s; __syncthreads();
    if (t < 16) {
        float tot = 0.f;
        #pragma unroll
        for (int g2 = 0; g2 < 16; g2++) tot += red[g2*16 + t];
        d_cols[i*CC + t] = tot;
        atomicAdd(&d_all[t], tot);
        size_t di = ((size_t)i*LN + i)*CC + t;
        float dv = mask_at(M, di, mdt) ? T[di] : 0.f;
        d_diag[i*CC + t] = dv;
        atomicAdd(&d_trace[t], dv);
    }
}

// ===================== launch 2: rowsum (read-only over Tm) =================
__global__ void k_rowsum()
{
    const int q = blockIdx.x, t = threadIdx.x;
    const int c = t & 15, g = t >> 4;
    float s = 0.f;
    for (int l = g; l < LN; l += 16)
        s += d_Tm[((size_t)l*LN + q)*CC + c];
    __shared__ float red[256];
    red[t] = s; __syncthreads();
    if (t < 16) {
        float tot = 0.f;
        #pragma unroll
        for (int g2 = 0; g2 < 16; g2++) tot += red[g2*16 + t];
        d_rows[q*CC + t] = tot;
    }
}

// ===================== launch 3: Afull / CB / D (4-way split + shfl) ========
// block = one node, 256 threads: o = t>>2 (64 outputs), part = t&3 (c quarter)
__global__ void k_prep_ACD(const float* __restrict__ W1, const float* __restrict__ b1)
{
    const int node = blockIdx.x;
    const int t = threadIdx.x;
    const int o = t >> 2, part = t & 3;
    __shared__ float sd[16], sr[16], sc[16], st[16], sa[16];
    if (t < 16) {
        sd[t] = d_diag[node*CC + t]; sr[t] = d_rows[node*CC + t];
        sc[t] = d_cols[node*CC + t]; st[t] = d_trace[t]; sa[t] = d_all[t];
    }
    __syncthreads();
    const float* w = W1 + o*240;
    float A = 0.f, CB = 0.f, D = 0.f;
    const int c0 = part * 4;
    #pragma unroll
    for (int e = 0; e < 4; e++) {
        int c = c0 + e;
        A  = fmaf(w[ 1*16 + c], sd[c], A);
        A  = fmaf(w[ 9*16 + c], sr[c], A);
        A  = fmaf(w[10*16 + c], sc[c], A);
        CB = fmaf(w[ 8*16 + c], st[c], CB);
        CB = fmaf(w[14*16 + c], sa[c], CB);
        CB = fmaf(w[ 2*16 + c], sd[c], CB);
        CB = fmaf(w[12*16 + c], sc[c], CB);
        CB = fmaf(w[13*16 + c], sr[c], CB);
        D  = fmaf(w[ 0*16 + c], sd[c], D);
        D  = fmaf(w[ 3*16 + c], sr[c], D);
        D  = fmaf(w[ 4*16 + c], sc[c], D);
        D  = fmaf(w[ 5*16 + c], st[c], D);
        D  = fmaf(w[11*16 + c], sa[c], D);
    }
    // reduce across the 4 lanes sharing o (lanes o*4..o*4+3 within warp)
    A  += __shfl_xor_sync(0xffffffffu, A, 1);
    A  += __shfl_xor_sync(0xffffffffu, A, 2);
    CB += __shfl_xor_sync(0xffffffffu, CB, 1);
    CB += __shfl_xor_sync(0xffffffffu, CB, 2);
    D  += __shfl_xor_sync(0xffffffffu, D, 1);
    D  += __shfl_xor_sync(0xffffffffu, D, 2);
    if (part == 0) {
        d_Afull[node*NO + o] = A;
        d_CB[node*NO + o]    = CB + b1[o];
        d_D[node*NO + o]     = D;
    }
}

// ===================== launch 4: weight fragment layouts ====================
__global__ void k_prep_w(const float* __restrict__ W1, const float* __restrict__ W2)
{
    int idx = blockIdx.x * 256 + threadIdx.x;
    if (idx < 4*32*16) {
        int s = idx & 15, lane = (idx >> 4) & 31, k = idx >> 9;
        int n = s >> 1, h = s & 1, t4 = lane >> 2, tq = lane & 3;
        int col = k*8 + tq + 4*h;                 // 0..31
        int o = n*8 + t4;
        float v = (col < 16) ? W1[o*240 + 7*16 + col]
                             : W1[o*240 + 6*16 + (col - 16)];
        d_W1F[idx] = tf32f(v);
    } else if (idx < 4*32*16 + 8*32*16) {
        int q = idx - 4*32*16;
        int s = q & 15, lane = (q >> 4) & 31, k = q >> 9;
        int n = s >> 1, h = s & 1, t4 = lane >> 2, tq = lane & 3;
        int col = k*8 + tq + 4*h;                 // 0..63
        d_W2F[q] = tf32f(W2[(n*8 + t4)*64 + col]);
    }
}

// ===================== launch 5: main mma kernel ============================
// CTA: i = blockIdx.y, 128-wide j strip = blockIdx.x. 4 warps, each owns 32 rows.
__global__ __launch_bounds__(128)
void k_main_mma(const float* __restrict__ b2, float* __restrict__ out)
{
    __shared__ float buf[128 * PAD];

    const int tid = threadIdx.x;
    const int wid = tid >> 5, lane = tid & 31;
    const int t4 = lane >> 2, tq = lane & 3;
    const int i  = blockIdx.y;
    const int j0 = blockIdx.x * 128;

    // ---- X build ----
    // cols 0..15: Tm(i, j0+r, :)  coalesced strip
    const float4* TmV = reinterpret_cast<const float4*>(d_Tm) + ((size_t)i*LN + j0)*4;
    #pragma unroll
    for (int s = 0; s < 4; s++) {
        int idx = s*128 + tid;            // 0..511
        int r = idx >> 2, q = idx & 3;
        *reinterpret_cast<float4*>(&buf[r*PAD + q*4]) = TmV[r*4 + q];
    }
    // cols 16..31: Tm(j0+r, i, :)  scattered 64B rows (L2-resident)
    {
        const int r = tid;
        const float4* Tt4 = reinterpret_cast<const float4*>(
            d_Tm + ((size_t)(j0 + r)*LN + i)*CC);
        float4 a = Tt4[0], b = Tt4[1], c = Tt4[2], d = Tt4[3];
        *reinterpret_cast<float4*>(&buf[r*PAD + 16])  = a;
        *reinterpret_cast<float4*>(&buf[r*PAD + 20])  = b;
        *reinterpret_cast<float4*>(&buf[r*PAD + 24])  = c;
        *reinterpret_cast<float4*>(&buf[r*PAD + 28])  = d;
    }
    __syncthreads();

    const float* bufw = buf + wid * 32 * PAD;

    // ---- GEMM1: u[32x64] = X[32x32] @ Wf^T (4 k-tiles) -------------------
    float u[2][8][4];
    #pragma unroll
    for (int m = 0; m < 2; m++)
        #pragma unroll
        for (int n = 0; n < 8; n++)
            #pragma unroll
            for (int c = 0; c < 4; c++) u[m][n][c] = 0.f;

    #pragma unroll
    for (int k = 0; k < 4; k++) {
        uint32_t a[2][4];
        #pragma unroll
        for (int m = 0; m < 2; m++) {
            const float* pr = bufw + (m*16 + t4)*PAD + k*8 + tq;
            a[m][0] = __float_as_uint(pr[0]);
            a[m][1] = __float_as_uint(pr[8*PAD]);
            a[m][2] = __float_as_uint(pr[4]);
            a[m][3] = __float_as_uint(pr[8*PAD + 4]);
        }
        float4 bq[4];
        const float4* wp = reinterpret_cast<const float4*>(d_W1F + (k*32 + lane)*16);
        bq[0] = wp[0]; bq[1] = wp[1]; bq[2] = wp[2]; bq[3] = wp[3];
        const uint32_t* bb = reinterpret_cast<const uint32_t*>(bq);
        #pragma unroll
        for (int n = 0; n < 8; n++) {
            mma8(u[0][n], a[0], bb[2*n], bb[2*n+1]);
            mma8(u[1][n], a[1], bb[2*n], bb[2*n+1]);
        }
    }

    // ---- epilogue 1: + A[j] + CB[i] (+D diag), relu, tf32, store ---------
    float2 cb[8];
    #pragma unroll
    for (int n = 0; n < 8; n++)
        cb[n] = *reinterpret_cast<const float2*>(d_CB + i*NO + n*8 + 2*tq);

    #pragma unroll
    for (int m = 0; m < 2; m++) {
        const int r1 = wid*32 + m*16 + t4, r2 = r1 + 8;
        const int j1 = j0 + r1, j2 = j0 + r2;
        #pragma unroll
        for (int n = 0; n < 8; n++) {
            const int col = n*8 + 2*tq;
            float2 A1 = *reinterpret_cast<const float2*>(d_Afull + (size_t)j1*NO + col);
            float2 A2 = *reinterpret_cast<const float2*>(d_Afull + (size_t)j2*NO + col);
            float v0 = u[m][n][0] + A1.x + cb[n].x;
            float v1 = u[m][n][1] + A1.y + cb[n].y;
            float v2 = u[m][n][2] + A2.x + cb[n].x;
            float v3 = u[m][n][3] + A2.y + cb[n].y;
            if (j1 == i) {
                float2 dd = *reinterpret_cast<const float2*>(d_D + i*NO + col);
                v0 += dd.x; v1 += dd.y;
            }
            if (j2 == i) {
                float2 dd = *reinterpret_cast<const float2*>(d_D + i*NO + col);
                v2 += dd.x; v3 += dd.y;
            }
            float2 s1, s2;
            s1.x = tf32f(fmaxf(v0, 0.f)); s1.y = tf32f(fmaxf(v1, 0.f));
            s2.x = tf32f(fmaxf(v2, 0.f)); s2.y = tf32f(fmaxf(v3, 0.f));
            *reinterpret_cast<float2*>(&buf[r1*PAD + col]) = s1;
            *reinterpret_cast<float2*>(&buf[r2*PAD + col]) = s2;
        }
    }
    __syncwarp();

    // ---- GEMM2: out[32x64] = relu(u)[32x64] @ W2^T (8 k-tiles) -----------
    float o2[2][8][4];
    #pragma unroll
    for (int m = 0; m < 2; m++)
        #pragma unroll
        for (int n = 0; n < 8; n++)
            #pragma unroll
            for (int c = 0; c < 4; c++) o2[m][n][c] = 0.f;

    #pragma unroll
    for (int k = 0; k < 8; k++) {
        uint32_t a[2][4];
        #pragma unroll
        for (int m = 0; m < 2; m++) {
            const float* pr = bufw + (m*16 + t4)*PAD + k*8 + tq;
            a[m][0] = __float_as_uint(pr[0]);
            a[m][1] = __float_as_uint(pr[8*PAD]);
            a[m][2] = __float_as_uint(pr[4]);
            a[m][3] = __float_as_uint(pr[8*PAD + 4]);
        }
        float4 bq[4];
        const float4* wp = reinterpret_cast<const float4*>(d_W2F + (k*32 + lane)*16);
        bq[0] = wp[0]; bq[1] = wp[1]; bq[2] = wp[2]; bq[3] = wp[3];
        const uint32_t* bb = reinterpret_cast<const uint32_t*>(bq);
        #pragma unroll
        for (int n = 0; n < 8; n++) {
            mma8(o2[0][n], a[0], bb[2*n], bb[2*n+1]);
            mma8(o2[1][n], a[1], bb[2*n], bb[2*n+1]);
        }
    }

    // ---- epilogue 2: + b2, store -----------------------------------------
    float2 b2v[8];
    #pragma unroll
    for (int n = 0; n < 8; n++)
        b2v[n] = *reinterpret_cast<const float2*>(b2 + n*8 + 2*tq);

    #pragma unroll
    for (int m = 0; m < 2; m++) {
        const int r1 = wid*32 + m*16 + t4;
        const int j1 = j0 + r1, j2 = j1 + 8;
        float* o1 = out + ((size_t)i*LN + j1)*NO;
        float* o8 = out + ((size_t)i*LN + j2)*NO;
        #pragma unroll
        for (int n = 0; n < 8; n++) {
            const int col = n*8 + 2*tq;
            float2 s1, s2;
            s1.x = o2[m][n][0] + b2v[n].x; s1.y = o2[m][n][1] + b2v[n].y;
            s2.x = o2[m][n][2] + b2v[n].x; s2.y = o2[m][n][3] + b2v[n].y;
            *reinterpret_cast<float2*>(o1 + col) = s1;
            *reinterpret_cast<float2*>(o8 + col) = s2;
        }
    }
}

// ===================== launch ===============================================
extern "C" void kernel_launch(void* const* d_in, const int* in_sizes, int n_in,
                              void* d_out, int out_size)
{
    const float* T  = (const float*)d_in[0];
    const void*  M  = d_in[1];
    const float* W1 = (const float*)d_in[2];
    const float* b1 = (const float*)d_in[3];
    const float* W2 = (const float*)d_in[4];
    const float* b2 = (const float*)d_in[5];
    float*       out = (float*)d_out;

    k_detect<<<1, 256>>>((const unsigned char*)M);         // launch 0
    k_pass1<<<LN, 256>>>(T, M);                            // launch 1
    k_rowsum<<<LN, 256>>>();                               // launch 2
    k_prep_ACD<<<LN, 256>>>(W1, b1);                       // launch 3
    k_prep_w<<<24, 256>>>(W1, W2);                         // launch 4

    dim3 grid(LN/128, LN);
    k_main_mma<<<grid, 128>>>(b2, out);                    // launch 5
}

// round 8
// speedup vs baseline: 2.8018x; 1.0657x over previous
#include <cuda_runtime.h>
#include <cstdint>
#include <cstddef>

#define LN  1024
#define CC  16
#define NO  64
#define PAD 76      // buf row stride: 76 mod 32 = 12 -> conflict-free frag LDS/STS

// ===================== scratch globals ======================================
__device__ float d_Tm[LN*LN*CC];   // masked T, tf32-rounded
__device__ float d_diag[LN*CC];    // fp32
__device__ float d_rows[LN*CC];
__device__ float d_cols[LN*CC];
__device__ float d_trace[CC];
__device__ float d_all[CC];
// A-bias in mma fragment order: [strip][warp][m][h][n][lane] float2
__device__ float2 d_AF2[8*4*2*2*8*32];
__device__ float d_CB[LN*NO];      // fp32: b1+blk8@tr+blk14@all+blk2@diag+blk12@cols+blk13@rows
__device__ float d_D[LN*NO];       // fp32 diagonal extra
__device__ float d_W1F[4*32*16];   // GEMM1 B frags, tf32
__device__ float d_W2F[8*32*16];   // GEMM2 B frags, tf32
__device__ int   g_mdt;            // 0=uint8 bool, 1=int32, 2=float32

// ===================== helpers ==============================================
__device__ __forceinline__ float tf32f(float x) {
    uint32_t u;
    asm("cvt.rna.tf32.f32 %0, %1;" : "=r"(u) : "f"(x));
    return __uint_as_float(u);
}
__device__ __forceinline__ void mma8(float c[4], const uint32_t a[4],
                                     uint32_t b0, uint32_t b1) {
    asm volatile(
        "mma.sync.aligned.m16n8k8.row.col.f32.tf32.tf32.f32 "
        "{%0,%1,%2,%3}, {%4,%5,%6,%7}, {%8,%9}, {%0,%1,%2,%3};"
        : "+f"(c[0]), "+f"(c[1]), "+f"(c[2]), "+f"(c[3])
        : "r"(a[0]), "r"(a[1]), "r"(a[2]), "r"(a[3]), "r"(b0), "r"(b1));
}
__device__ __forceinline__ bool mask_at(const void* M, size_t idx, int mdt)
{
    if (mdt == 0) return ((const unsigned char*)M)[idx] != 0;
    if (mdt == 1) return ((const int*)M)[idx] != 0;
    return ((const float*)M)[idx] != 0.f;
}
__device__ __forceinline__ void stcs2(float* p, float x, float y)
{
    asm volatile("st.global.cs.v2.f32 [%0], {%1, %2};" :: "l"(p), "f"(x), "f"(y));
}

// ===================== launch 0: detect mask dtype (parallel) ==============
__global__ void k_detect(const unsigned char* __restrict__ M)
{
    __shared__ int sf32, su8;
    const int t = threadIdx.x;          // 256
    if (t == 0) { sf32 = 0; su8 = 0; }
    __syncthreads();
    int f32 = 0, u8 = 0;
    for (int w = t; w < 1024; w += 256) {
        unsigned b0 = M[4*w+0], b1 = M[4*w+1], b2 = M[4*w+2], b3 = M[4*w+3];
        if (b0 > 1u || b1 > 1u || b2 > 1u || b3 > 1u) f32 = 1;
        if (b1 | b2 | b3) u8 = 1;
    }
    if (f32) atomicOr(&sf32, 1);
    if (u8)  atomicOr(&su8, 1);
    __syncthreads();
    if (t == 0) g_mdt = sf32 ? 2 : (su8 ? 0 : 1);
    if (t < CC) { d_trace[t] = 0.f; d_all[t] = 0.f; }
}

// ===================== launch 1: mask+round -> Tm, colsum, diag, all/trace ==
__global__ void k_pass1(const float* __restrict__ T, const void* __restrict__ M)
{
    const int mdt = g_mdt;
    const int i = blockIdx.x, t = threadIdx.x;
    const int c = t & 15, g = t >> 4;
    float s = 0.f;
    for (int j = g; j < LN; j += 16) {
        size_t idx = ((size_t)i*LN + j)*CC + c;
        float v = mask_at(M, idx, mdt) ? T[idx] : 0.f;
        d_Tm[idx] = tf32f(v);
        s += v;
    }
    __shared__ float red[256];
    red[t] = s; __syncthreads();
    if (t < 16) {
        float tot = 0.f;
        #pragma unroll
        for (int g2 = 0; g2 < 16; g2++) tot += red[g2*16 + t];
        d_cols[i*CC + t] = tot;
        atomicAdd(&d_all[t], tot);
        size_t di = ((size_t)i*LN + i)*CC + t;
        float dv = mask_at(M, di, mdt) ? T[di] : 0.f;
        d_diag[i*CC + t] = dv;
        atomicAdd(&d_trace[t], dv);
    }
}

// ===================== launch 2: rowsum (read-only over Tm) =================
__global__ void k_rowsum()
{
    const int q = blockIdx.x, t = threadIdx.x;
    const int c = t & 15, g = t >> 4;
    float s = 0.f;
    for (int l = g; l < LN; l += 16)
        s += d_Tm[((size_t)l*LN + q)*CC + c];
    __shared__ float red[256];
    red[t] = s; __syncthreads();
    if (t < 16) {
        float tot = 0.f;
        #pragma unroll
        for (int g2 = 0; g2 < 16; g2++) tot += red[g2*16 + t];
        d_rows[q*CC + t] = tot;
    }
}

// ===================== launch 3: AF2 / CB / D ==============================
// block = one node j, 256 threads: o = t>>2, part = t&3 (c quarter), shfl reduce
__global__ void k_prep_ACD(const float* __restrict__ W1, const float* __restrict__ b1)
{
    const int node = blockIdx.x;
    const int t = threadIdx.x;
    const int o = t >> 2, part = t & 3;
    __shared__ float sd[16], sr[16], sc[16], st[16], sa[16];
    if (t < 16) {
        sd[t] = d_diag[node*CC + t]; sr[t] = d_rows[node*CC + t];
        sc[t] = d_cols[node*CC + t]; st[t] = d_trace[t]; sa[t] = d_all[t];
    }
    __syncthreads();
    const float* w = W1 + o*240;
    float A = 0.f, CB = 0.f, D = 0.f;
    const int c0 = part * 4;
    #pragma unroll
    for (int e = 0; e < 4; e++) {
        int c = c0 + e;
        A  = fmaf(w[ 1*16 + c], sd[c], A);
        A  = fmaf(w[ 9*16 + c], sr[c], A);
        A  = fmaf(w[10*16 + c], sc[c], A);
        CB = fmaf(w[ 8*16 + c], st[c], CB);
        CB = fmaf(w[14*16 + c], sa[c], CB);
        CB = fmaf(w[ 2*16 + c], sd[c], CB);
        CB = fmaf(w[12*16 + c], sc[c], CB);
        CB = fmaf(w[13*16 + c], sr[c], CB);
        D  = fmaf(w[ 0*16 + c], sd[c], D);
        D  = fmaf(w[ 3*16 + c], sr[c], D);
        D  = fmaf(w[ 4*16 + c], sc[c], D);
        D  = fmaf(w[ 5*16 + c], st[c], D);
        D  = fmaf(w[11*16 + c], sa[c], D);
    }
    A  += __shfl_xor_sync(0xffffffffu, A, 1);
    A  += __shfl_xor_sync(0xffffffffu, A, 2);
    CB += __shfl_xor_sync(0xffffffffu, CB, 1);
    CB += __shfl_xor_sync(0xffffffffu, CB, 2);
    D  += __shfl_xor_sync(0xffffffffu, D, 1);
    D  += __shfl_xor_sync(0xffffffffu, D, 2);
    if (part == 0) {
        // fragment-order A write: node -> (strip, warp, m, h, t4), o -> (n, tq, e)
        int strip = node >> 7, wd = (node >> 5) & 3;
        int m = (node >> 4) & 1, h = (node >> 3) & 1, t4r = node & 7;
        int n = o >> 3, tqr = (o >> 1) & 3, e = o & 1;
        int fi = (((((strip*4 + wd)*2 + m)*2 + h)*8 + n)*32) + t4r*4 + tqr;
        reinterpret_cast<float*>(d_AF2)[fi*2 + e] = A;
        d_CB[node*NO + o] = CB + b1[o];
        d_D[node*NO + o]  = D;
    }
}

// ===================== launch 4: weight fragment layouts ====================
__global__ void k_prep_w(const float* __restrict__ W1, const float* __restrict__ W2)
{
    int idx = blockIdx.x * 256 + threadIdx.x;
    if (idx < 4*32*16) {
        int s = idx & 15, lane = (idx >> 4) & 31, k = idx >> 9;
        int n = s >> 1, h = s & 1, t4 = lane >> 2, tq = lane & 3;
        int col = k*8 + tq + 4*h;                 // 0..31
        int o = n*8 + t4;
        float v = (col < 16) ? W1[o*240 + 7*16 + col]
                             : W1[o*240 + 6*16 + (col - 16)];
        d_W1F[idx] = tf32f(v);
    } else if (idx < 4*32*16 + 8*32*16) {
        int q = idx - 4*32*16;
        int s = q & 15, lane = (q >> 4) & 31, k = q >> 9;
        int n = s >> 1, h = s & 1, t4 = lane >> 2, tq = lane & 3;
        int col = k*8 + tq + 4*h;                 // 0..63
        d_W2F[q] = tf32f(W2[(n*8 + t4)*64 + col]);
    }
}

// ===================== launch 5: main mma kernel ============================
__global__ __launch_bounds__(128)
void k_main_mma(const float* __restrict__ b2, float* __restrict__ out)
{
    __shared__ float buf[128 * PAD];

    const int tid = threadIdx.x;
    const int wid = tid >> 5, lane = tid & 31;
    const int t4 = lane >> 2, tq = lane & 3;
    const int i  = blockIdx.y;
    const int j0 = blockIdx.x * 128;

    // ---- X build ----
    const float4* TmV = reinterpret_cast<const float4*>(d_Tm) + ((size_t)i*LN + j0)*4;
    #pragma unroll
    for (int s = 0; s < 4; s++) {
        int idx = s*128 + tid;
        int r = idx >> 2, q = idx & 3;
        *reinterpret_cast<float4*>(&buf[r*PAD + q*4]) = TmV[r*4 + q];
    }
    {
        const int r = tid;
        const float4* Tt4 = reinterpret_cast<const float4*>(
            d_Tm + ((size_t)(j0 + r)*LN + i)*CC);
        float4 a = Tt4[0], b = Tt4[1], c = Tt4[2], d = Tt4[3];
        *reinterpret_cast<float4*>(&buf[r*PAD + 16])  = a;
        *reinterpret_cast<float4*>(&buf[r*PAD + 20])  = b;
        *reinterpret_cast<float4*>(&buf[r*PAD + 24])  = c;
        *reinterpret_cast<float4*>(&buf[r*PAD + 28])  = d;
    }
    __syncthreads();

    const float* bufw = buf + wid * 32 * PAD;

    // ---- GEMM1: u[32x64] = X[32x32] @ Wf^T (4 k-tiles) -------------------
    float u[2][8][4];
    #pragma unroll
    for (int m = 0; m < 2; m++)
        #pragma unroll
        for (int n = 0; n < 8; n++)
            #pragma unroll
            for (int c = 0; c < 4; c++) u[m][n][c] = 0.f;

    #pragma unroll
    for (int k = 0; k < 4; k++) {
        uint32_t a[2][4];
        #pragma unroll
        for (int m = 0; m < 2; m++) {
            const float* pr = bufw + (m*16 + t4)*PAD + k*8 + tq;
            a[m][0] = __float_as_uint(pr[0]);
            a[m][1] = __float_as_uint(pr[8*PAD]);
            a[m][2] = __float_as_uint(pr[4]);
            a[m][3] = __float_as_uint(pr[8*PAD + 4]);
        }
        float4 bq[4];
        const float4* wp = reinterpret_cast<const float4*>(d_W1F + (k*32 + lane)*16);
        bq[0] = wp[0]; bq[1] = wp[1]; bq[2] = wp[2]; bq[3] = wp[3];
        const uint32_t* bb = reinterpret_cast<const uint32_t*>(bq);
        #pragma unroll
        for (int n = 0; n < 8; n++) {
            mma8(u[0][n], a[0], bb[2*n], bb[2*n+1]);
            mma8(u[1][n], a[1], bb[2*n], bb[2*n+1]);
        }
    }

    // ---- epilogue 1: + A (fragment-order, coalesced) + CB[i] (+D), relu --
    float2 cb[8];
    #pragma unroll
    for (int n = 0; n < 8; n++)
        cb[n] = *reinterpret_cast<const float2*>(d_CB + i*NO + n*8 + 2*tq);

    const float2* afBase = d_AF2 + ((size_t)blockIdx.x*4 + wid)*2*2*8*32;

    #pragma unroll
    for (int m = 0; m < 2; m++) {
        const int r1 = wid*32 + m*16 + t4, r2 = r1 + 8;
        const int j1 = j0 + r1, j2 = j0 + r2;
        const float2* af0 = afBase + (m*2 + 0)*8*32;   // h=0 rows
        const float2* af1 = afBase + (m*2 + 1)*8*32;   // h=1 rows
        #pragma unroll
        for (int n = 0; n < 8; n++) {
            const int col = n*8 + 2*tq;
            float2 A1 = af0[n*32 + lane];
            float2 A2 = af1[n*32 + lane];
            float v0 = u[m][n][0] + A1.x + cb[n].x;
            float v1 = u[m][n][1] + A1.y + cb[n].y;
            float v2 = u[m][n][2] + A2.x + cb[n].x;
            float v3 = u[m][n][3] + A2.y + cb[n].y;
            if (j1 == i) {
                float2 dd = *reinterpret_cast<const float2*>(d_D + i*NO + col);
                v0 += dd.x; v1 += dd.y;
            }
            if (j2 == i) {
                float2 dd = *reinterpret_cast<const float2*>(d_D + i*NO + col);
                v2 += dd.x; v3 += dd.y;
            }
            float2 s1, s2;
            s1.x = tf32f(fmaxf(v0, 0.f)); s1.y = tf32f(fmaxf(v1, 0.f));
            s2.x = tf32f(fmaxf(v2, 0.f)); s2.y = tf32f(fmaxf(v3, 0.f));
            *reinterpret_cast<float2*>(&buf[r1*PAD + col]) = s1;
            *reinterpret_cast<float2*>(&buf[r2*PAD + col]) = s2;
        }
    }
    __syncwarp();

    // ---- GEMM2: out[32x64] = relu(u)[32x64] @ W2^T (8 k-tiles) -----------
    float o2[2][8][4];
    #pragma unroll
    for (int m = 0; m < 2; m++)
        #pragma unroll
        for (int n = 0; n < 8; n++)
            #pragma unroll
            for (int c = 0; c < 4; c++) o2[m][n][c] = 0.f;

    #pragma unroll
    for (int k = 0; k < 8; k++) {
        uint32_t a[2][4];
        #pragma unroll
        for (int m = 0; m < 2; m++) {
            const float* pr = bufw + (m*16 + t4)*PAD + k*8 + tq;
            a[m][0] = __float_as_uint(pr[0]);
            a[m][1] = __float_as_uint(pr[8*PAD]);
            a[m][2] = __float_as_uint(pr[4]);
            a[m][3] = __float_as_uint(pr[8*PAD + 4]);
        }
        float4 bq[4];
        const float4* wp = reinterpret_cast<const float4*>(d_W2F + (k*32 + lane)*16);
        bq[0] = wp[0]; bq[1] = wp[1]; bq[2] = wp[2]; bq[3] = wp[3];
        const uint32_t* bb = reinterpret_cast<const uint32_t*>(bq);
        #pragma unroll
        for (int n = 0; n < 8; n++) {
            mma8(o2[0][n], a[0], bb[2*n], bb[2*n+1]);
            mma8(o2[1][n], a[1], bb[2*n], bb[2*n+1]);
        }
    }

    // ---- epilogue 2: + b2, streaming store -------------------------------
    float2 b2v[8];
    #pragma unroll
    for (int n = 0; n < 8; n++)
        b2v[n] = *reinterpret_cast<const float2*>(b2 + n*8 + 2*tq);

    #pragma unroll
    for (int m = 0; m < 2; m++) {
        const int r1 = wid*32 + m*16 + t4;
        const int j1 = j0 + r1, j2 = j1 + 8;
        float* o1 = out + ((size_t)i*LN + j1)*NO;
        float* o8 = out + ((size_t)i*LN + j2)*NO;
        #pragma unroll
        for (int n = 0; n < 8; n++) {
            const int col = n*8 + 2*tq;
            stcs2(o1 + col, o2[m][n][0] + b2v[n].x, o2[m][n][1] + b2v[n].y);
            stcs2(o8 + col, o2[m][n][2] + b2v[n].x, o2[m][n][3] + b2v[n].y);
        }
    }
}

// ===================== launch ===============================================
extern "C" void kernel_launch(void* const* d_in, const int* in_sizes, int n_in,
                              void* d_out, int out_size)
{
    const float* T  = (const float*)d_in[0];
    const void*  M  = d_in[1];
    const float* W1 = (const float*)d_in[2];
    const float* b1 = (const float*)d_in[3];
    const float* W2 = (const float*)d_in[4];
    const float* b2 = (const float*)d_in[5];
    float*       out = (float*)d_out;

    k_detect<<<1, 256>>>((const unsigned char*)M);         // launch 0
    k_pass1<<<LN, 256>>>(T, M);                            // launch 1
    k_rowsum<<<LN, 256>>>();                               // launch 2
    k_prep_ACD<<<LN, 256>>>(W1, b1);                       // launch 3
    k_prep_w<<<24, 256>>>(W1, W2);                         // launch 4

    dim3 grid(LN/128, LN);
    k_main_mma<<<grid, 128>>>(b2, out);                    // launch 5
}